// round 1
// baseline (speedup 1.0000x reference)
#include <cuda_runtime.h>
#include <cuda_bf16.h>

#define NN 8192
#define DD 256
#define HH 64
#define DEG 32

// Scratch: Q, K, V  [NN x HH] each
__device__ float g_Q[NN * HH];
__device__ float g_K[NN * HH];
__device__ float g_V[NN * HH];

// ---------------------------------------------------------------------------
// Kernel 1: QKV projections.  grid = (NN/64, 3), block = 256.
// blockIdx.y selects matrix (0=Q,1=K,2=V). Classic smem-tiled fp32 GEMM:
// BM=64, BN=64, BK=64, 4x4 microtile per thread.
// ---------------------------------------------------------------------------
__global__ __launch_bounds__(256) void qkv_gemm(
    const float* __restrict__ x,
    const float* __restrict__ Wq, const float* __restrict__ bq,
    const float* __restrict__ Wk, const float* __restrict__ bk,
    const float* __restrict__ Wv)
{
    const int mat = blockIdx.y;
    const float* __restrict__ W = (mat == 0) ? Wq : (mat == 1) ? Wk : Wv;
    const float* __restrict__ bias = (mat == 0) ? bq : (mat == 1) ? bk : nullptr;
    float* __restrict__ O = (mat == 0) ? g_Q : (mat == 1) ? g_K : g_V;

    const int rowBase = blockIdx.x * 64;

    __shared__ __align__(16) float As[64][64];  // [m][k]  (direct copy of x tile)
    __shared__ __align__(16) float Bs[64][64];  // [k][n]

    const int t  = threadIdx.x;      // 0..255
    const int tr = t >> 4;           // 0..15 (row group)
    const int tc = t & 15;           // 0..15 (col group)

    float acc[4][4];
#pragma unroll
    for (int i = 0; i < 4; i++)
#pragma unroll
        for (int j = 0; j < 4; j++) acc[i][j] = 0.f;

    for (int k0 = 0; k0 < DD; k0 += 64) {
        // Load A tile: 64x64 floats = 1024 float4, 4 per thread
#pragma unroll
        for (int q = 0; q < 4; q++) {
            int i4 = t * 4 + q;            // 0..1023
            int m  = i4 >> 4;              // 0..63
            int kk = (i4 & 15) << 2;       // 0..60
            float4 v = *(const float4*)&x[(size_t)(rowBase + m) * DD + k0 + kk];
            *(float4*)&As[m][kk] = v;
        }
        // Load B tile: W[(k0+kk)*64 + n]
#pragma unroll
        for (int q = 0; q < 4; q++) {
            int i4 = t * 4 + q;
            int kk = i4 >> 4;              // 0..63
            int n  = (i4 & 15) << 2;       // 0..60
            float4 v = *(const float4*)&W[(size_t)(k0 + kk) * HH + n];
            *(float4*)&Bs[kk][n] = v;
        }
        __syncthreads();

#pragma unroll
        for (int k = 0; k < 64; k++) {
            float a0 = As[tr * 4 + 0][k];
            float a1 = As[tr * 4 + 1][k];
            float a2 = As[tr * 4 + 2][k];
            float a3 = As[tr * 4 + 3][k];
            float4 b = *(const float4*)&Bs[k][tc * 4];
            acc[0][0] += a0 * b.x; acc[0][1] += a0 * b.y; acc[0][2] += a0 * b.z; acc[0][3] += a0 * b.w;
            acc[1][0] += a1 * b.x; acc[1][1] += a1 * b.y; acc[1][2] += a1 * b.z; acc[1][3] += a1 * b.w;
            acc[2][0] += a2 * b.x; acc[2][1] += a2 * b.y; acc[2][2] += a2 * b.z; acc[2][3] += a2 * b.w;
            acc[3][0] += a3 * b.x; acc[3][1] += a3 * b.y; acc[3][2] += a3 * b.z; acc[3][3] += a3 * b.w;
        }
        __syncthreads();
    }

    // Epilogue: bias add (Q,K only) + coalesced float4 stores
    float4 bv = make_float4(0.f, 0.f, 0.f, 0.f);
    if (bias) bv = *(const float4*)&bias[tc * 4];
#pragma unroll
    for (int i = 0; i < 4; i++) {
        int row = rowBase + tr * 4 + i;
        float4 o;
        o.x = acc[i][0] + bv.x;
        o.y = acc[i][1] + bv.y;
        o.z = acc[i][2] + bv.z;
        o.w = acc[i][3] + bv.w;
        *(float4*)&O[(size_t)row * HH + tc * 4] = o;
    }
}

// ---------------------------------------------------------------------------
// Kernel 2: sparse attention + V aggregation. One warp per node.
// Lane l owns output columns 2l, 2l+1 and edge l (each node has exactly 32 edges).
// ---------------------------------------------------------------------------
__global__ __launch_bounds__(256) void attn_kernel(
    const int* __restrict__ dst,
    const int* __restrict__ edge_type,
    const float* __restrict__ edge_k_emb,
    float* __restrict__ out)
{
    const unsigned FULL = 0xffffffffu;
    const int lane = threadIdx.x & 31;
    const int warp = threadIdx.x >> 5;
    const int node = blockIdx.x * 8 + warp;

    // Q row, 2 floats per lane (coalesced)
    float2 q = ((const float2*)g_Q)[node * 32 + lane];

    // This lane's edge
    const int e  = node * DEG + lane;
    const int j  = dst[e];
    const float ek = edge_k_emb[edge_type[e]];

    // Partial dots: s[k] = contribution of columns (2l,2l+1) to edge k's score
    float s[DEG];
#pragma unroll
    for (int k = 0; k < DEG; k++) {
        int jk = __shfl_sync(FULL, j, k);
        float2 kv = ((const float2*)g_K)[jk * 32 + lane];
        s[k] = q.x * kv.x + q.y * kv.y;
    }

    // Transpose-reduce: lane l ends with the full dot for edge l (31 shfls)
#pragma unroll
    for (int off = 16; off >= 1; off >>= 1) {
        const bool hi = (lane & off) != 0;
#pragma unroll
        for (int k = 0; k < 16; k++) {
            if (k < off) {
                float keep = hi ? s[k + off] : s[k];
                float send = hi ? s[k] : s[k + off];
                s[k] = keep + __shfl_xor_sync(FULL, send, off);
            }
        }
    }
    // score = ((Q.K + ek)/H) / sqrt(H) = (dot + ek) / 512
    float score = (s[0] + ek) * (1.0f / 512.0f);

    // Warp softmax over the 32 edge scores (masked entries underflow to 0)
    float m = score;
#pragma unroll
    for (int off = 16; off >= 1; off >>= 1)
        m = fmaxf(m, __shfl_xor_sync(FULL, m, off));
    float ex = __expf(score - m);
    float sum = ex;
#pragma unroll
    for (int off = 16; off >= 1; off >>= 1)
        sum += __shfl_xor_sync(FULL, sum, off);
    float p = ex / sum;

    // Weighted sum of V rows: broadcast (p_k, j_k), coalesced float2 loads
    float2 acc = make_float2(0.f, 0.f);
#pragma unroll
    for (int k = 0; k < DEG; k++) {
        float pk = __shfl_sync(FULL, p, k);
        int jk   = __shfl_sync(FULL, j, k);
        float2 v = ((const float2*)g_V)[jk * 32 + lane];
        acc.x += pk * v.x;
        acc.y += pk * v.y;
    }

    ((float2*)out)[node * 32 + lane] = acc;
}

// ---------------------------------------------------------------------------
// Launch
// ---------------------------------------------------------------------------
extern "C" void kernel_launch(void* const* d_in, const int* in_sizes, int n_in,
                              void* d_out, int out_size)
{
    const float* x          = (const float*)d_in[0];
    // d_in[1] = src (implied by construction; unused)
    const int*   dst        = (const int*)d_in[2];
    const int*   edge_type  = (const int*)d_in[3];
    const float* W_q        = (const float*)d_in[4];
    const float* b_q        = (const float*)d_in[5];
    const float* W_k        = (const float*)d_in[6];
    const float* b_k        = (const float*)d_in[7];
    const float* W_v        = (const float*)d_in[8];
    const float* edge_k_emb = (const float*)d_in[9];
    float* out = (float*)d_out;

    dim3 g1(NN / 64, 3);
    qkv_gemm<<<g1, 256>>>(x, W_q, b_q, W_k, b_k, W_v);

    attn_kernel<<<NN / 8, 256>>>(dst, edge_type, edge_k_emb, out);
}